// round 8
// baseline (speedup 1.0000x reference)
#include <cuda_runtime.h>
#include <cuda_bf16.h>

#define N_ 384
#define D_ 256
#define H_ 8
#define DH_ 32
#define SCALE_ 0.17677669529663687f
#define L2E_ 1.4426950408889634f

typedef unsigned long long u64;

// ---------------- scratch (device globals; no allocation allowed) ----------
__device__ __align__(16) float g_KQ[N_*H_*D_];   // [n][h][d] scale folded
__device__ __align__(16) float g_CK[N_*H_*D_];   // [n][h][d] scale folded
__device__ __align__(16) float g_PV[N_*H_*D_];   // [n][h][c]
__device__ __align__(16) float g_WE[N_*H_*D_];   // normalized weighted e-sum
__device__ __align__(16) float g_CB[N_*H_];
__device__ __align__(16) float g_SB[N_*H_];
__device__ __align__(16) float g_SI[(size_t)N_*N_*H_];   // [i][j][h]

// ---------------- packed f32x2 helpers -------------------------------------
union F2U { float2 f; u64 u; };

__device__ __forceinline__ void dfma2(u64 &d, u64 a, u64 b) {
    asm("fma.rn.f32x2 %0, %1, %2, %0;" : "+l"(d) : "l"(a), "l"(b));
}
__device__ __forceinline__ u64 bcast2(float v) {
    F2U t; t.f.x = v; t.f.y = v; return t.u;
}
__device__ __forceinline__ float hsum2(u64 a) {
    F2U t; t.u = a; return t.f.x + t.f.y;
}
__device__ __forceinline__ u64 pack2f(float a, float b) {
    F2U t; t.f.x = a; t.f.y = b; return t.u;
}
// 5-round butterfly (redux.f32 does not exist on sm_103)
__device__ __forceinline__ float wredux(float v) {
    #pragma unroll
    for (int o = 16; o; o >>= 1) v += __shfl_xor_sync(0xffffffffu, v, o);
    return v;
}

// ---------------- P: per-node precompute -----------------------------------
__global__ void kP(const float* __restrict__ x,
                   const float* __restrict__ Wq_x, const float* __restrict__ bq_x,
                   const float* __restrict__ Wk_x, const float* __restrict__ bk_x,
                   const float* __restrict__ Wv_x, const float* __restrict__ bv_x,
                   const float* __restrict__ Wk_e, const float* __restrict__ bk_e,
                   const float* __restrict__ Wq_e, const float* __restrict__ bq_e,
                   const float* __restrict__ WOe)
{
    __shared__ float x_s[8][D_];
    __shared__ float q_s[8][H_][DH_];
    __shared__ float k_s[8][H_][DH_];
    __shared__ float v_s[8][H_][DH_];
    const int t  = threadIdx.x;
    const int n0 = blockIdx.x * 8;

    #pragma unroll
    for (int n = 0; n < 8; n++) x_s[n][t] = x[(n0 + n) * D_ + t];
    __syncthreads();

    {
        const int h = t >> 5, k = t & 31;
        float aq[8], ak[8], av[8];
        const float bq = bq_x[h*DH_ + k], bk = bk_x[h*DH_ + k], bv = bv_x[h*DH_ + k];
        #pragma unroll
        for (int n = 0; n < 8; n++) { aq[n] = bq; ak[n] = bk; av[n] = bv; }
        for (int d = 0; d < D_; d++) {
            const float wq = Wq_x[(h*D_ + d)*DH_ + k];
            const float wk = Wk_x[(h*D_ + d)*DH_ + k];
            const float wv = Wv_x[(h*D_ + d)*DH_ + k];
            #pragma unroll
            for (int n = 0; n < 8; n++) {
                const float xv = x_s[n][d];
                aq[n] += xv * wq; ak[n] += xv * wk; av[n] += xv * wv;
            }
        }
        #pragma unroll
        for (int n = 0; n < 8; n++) {
            q_s[n][h][k] = aq[n]; k_s[n][h][k] = ak[n]; v_s[n][h][k] = av[n];
        }
    }
    __syncthreads();

    if (t < 64) {
        const int n = t >> 3, hh = t & 7;
        float cb = 0.f, sb = 0.f;
        #pragma unroll
        for (int kk = 0; kk < DH_; kk++) {
            cb += q_s[n][hh][kk] * bk_e[hh*DH_ + kk];
            sb += k_s[n][hh][kk] * bq_e[hh*DH_ + kk];
        }
        g_CB[(n0 + n)*H_ + hh] = cb * SCALE_;
        g_SB[(n0 + n)*H_ + hh] = sb * SCALE_;
    }

    const int d = t;
    for (int n = 0; n < 8; n++) {
        for (int hh = 0; hh < H_; hh++) {
            float akq = 0.f, ack = 0.f;
            const float4* Wk4 = (const float4*)(Wk_e + (hh*D_ + d)*DH_);
            const float4* Wq4 = (const float4*)(Wq_e + (hh*D_ + d)*DH_);
            const float4* qs4 = (const float4*)(q_s[n][hh]);
            const float4* ks4 = (const float4*)(k_s[n][hh]);
            #pragma unroll
            for (int kk = 0; kk < 8; kk++) {
                const float4 w  = Wk4[kk], q = qs4[kk];
                akq += w.x*q.x + w.y*q.y + w.z*q.z + w.w*q.w;
                const float4 w2 = Wq4[kk], kx4 = ks4[kk];
                ack += w2.x*kx4.x + w2.y*kx4.y + w2.z*kx4.z + w2.w*kx4.w;
            }
            float apv = 0.f;
            #pragma unroll
            for (int kk = 0; kk < DH_; kk++)
                apv += v_s[n][hh][kk] * WOe[(hh*DH_ + kk)*D_ + d];
            const int base = ((n0 + n)*H_ + hh)*D_ + d;
            g_KQ[base] = akq * SCALE_;
            g_CK[base] = ack * SCALE_;
            g_PV[base] = apv;
        }
    }
}

// ---------------- M1: row pass -- s_en softmax + we, s_i store --------------
// Block = row i. Warp w: hg = w&1 (4 heads), jg = w>>1 (j mod 4).
// No block barrier in main loop; warp-private e loads; butterfly reduces.
__global__ void __launch_bounds__(256) kM1(const float* __restrict__ e)
{
    __shared__ float we_s[4][H_][D_];     // [jg][head][ch]
    __shared__ float ls_s[4][H_];
    const int i  = blockIdx.x;
    const int w  = threadIdx.x >> 5, l = threadIdx.x & 31;
    const int hg = w & 1, jg = w >> 1;
    const int hb = hg * 4;

    u64 kq[4][4], ck[4][4];
    #pragma unroll
    for (int hh = 0; hh < 4; hh++) {
        const float2* kp = (const float2*)(g_KQ + (i*H_ + hb + hh)*D_ + 8*l);
        const float2* cp = (const float2*)(g_CK + (i*H_ + hb + hh)*D_ + 8*l);
        #pragma unroll
        for (int r = 0; r < 4; r++) { F2U a; a.f = kp[r]; kq[hh][r] = a.u;
                                      F2U b; b.f = cp[r]; ck[hh][r] = b.u; }
    }
    const float4 cb4 = *(const float4*)(g_CB + i*H_ + hb);
    const float4 sb4 = *(const float4*)(g_SB + i*H_ + hb);

    u64 we[4][4];
    #pragma unroll
    for (int hh = 0; hh < 4; hh++)
        #pragma unroll
        for (int r = 0; r < 4; r++) we[hh][r] = 0ull;
    float lsum[4] = {0.f, 0.f, 0.f, 0.f};

    const float4* erow = (const float4*)(e + (u64)i*N_*D_);

    for (int j = jg; j < N_; j += 4) {
        const float4 ea = erow[j*64 + 2*l];
        const float4 eb = erow[j*64 + 2*l + 1];
        u64 ev[4];
        ev[0] = pack2f(ea.x, ea.y); ev[1] = pack2f(ea.z, ea.w);
        ev[2] = pack2f(eb.x, eb.y); ev[3] = pack2f(eb.z, eb.w);

        float dq[4], ds[4];
        #pragma unroll
        for (int hh = 0; hh < 4; hh++) {
            u64 aq = 0ull, as = 0ull;
            #pragma unroll
            for (int r = 0; r < 4; r++) { dfma2(aq, ev[r], kq[hh][r]); dfma2(as, ev[r], ck[hh][r]); }
            dq[hh] = hsum2(aq); ds[hh] = hsum2(as);
        }
        #pragma unroll
        for (int hh = 0; hh < 4; hh++) { dq[hh] = wredux(dq[hh]); ds[hh] = wredux(ds[hh]); }

        if (l == 0)
            *(float4*)(g_SI + ((u64)i*N_ + j)*H_ + hb) =
                make_float4(ds[0] + sb4.x, ds[1] + sb4.y, ds[2] + sb4.z, ds[3] + sb4.w);

        // scores O(+-5): exp2 cannot overflow; softmax shift-invariant.
        const float p0 = exp2f((dq[0] + cb4.x) * L2E_);
        const float p1 = exp2f((dq[1] + cb4.y) * L2E_);
        const float p2 = exp2f((dq[2] + cb4.z) * L2E_);
        const float p3 = exp2f((dq[3] + cb4.w) * L2E_);
        lsum[0] += p0; lsum[1] += p1; lsum[2] += p2; lsum[3] += p3;
        const u64 q0 = bcast2(p0), q1 = bcast2(p1), q2 = bcast2(p2), q3 = bcast2(p3);
        #pragma unroll
        for (int r = 0; r < 4; r++) {
            dfma2(we[0][r], q0, ev[r]); dfma2(we[1][r], q1, ev[r]);
            dfma2(we[2][r], q2, ev[r]); dfma2(we[3][r], q3, ev[r]);
        }
    }

    // combine partials across jg warps
    #pragma unroll
    for (int hh = 0; hh < 4; hh++)
        #pragma unroll
        for (int r = 0; r < 4; r++) {
            F2U a; a.u = we[hh][r];
            *(float2*)&we_s[jg][hb + hh][8*l + 2*r] = a.f;
        }
    if (l == 0)
        *(float4*)&ls_s[jg][hb] = make_float4(lsum[0], lsum[1], lsum[2], lsum[3]);
    __syncthreads();

    const int t = threadIdx.x;
    #pragma unroll
    for (int h = 0; h < H_; h++) {
        const float v  = we_s[0][h][t] + we_s[1][h][t] + we_s[2][h][t] + we_s[3][h][t];
        const float ls = ls_s[0][h] + ls_s[1][h] + ls_s[2][h] + ls_s[3][h];
        g_WE[((u64)i*H_ + h)*D_ + t] = v * __fdividef(1.f, ls);
    }
}

// ---------------- M2: column pass -- s_j, 2-way softmax, FULL e_out ---------
// Block = col j. Warp w: hg = w&1 (4 heads + eout channel half), ig = w>>1
// (i mod 4). Pair (hg=0,1) exchanges ai/aj via named barrier (id 1+ig, 64 thr).
// Writes final e_out = sum_h ai*pv_i + aj*pv_j + bOe  (kM3 fused away).
__global__ void __launch_bounds__(256) kM2(const float* __restrict__ e,
                                           const float* __restrict__ bOe,
                                           float* __restrict__ eout)
{
    __shared__ float ai_s[2][4][H_];   // [buf][ig][head]
    __shared__ float aj_s[2][4][H_];
    const int j  = blockIdx.x;
    const int w  = threadIdx.x >> 5, l = threadIdx.x & 31;
    const int hg = w & 1, ig = w >> 1;
    const int hb = hg * 4;
    const int ch = hg * 128 + 4 * l;           // float4 channel base

    u64 ck[4][4];
    #pragma unroll
    for (int hh = 0; hh < 4; hh++) {
        const float2* cp = (const float2*)(g_CK + (j*H_ + hb + hh)*D_ + 8*l);
        #pragma unroll
        for (int r = 0; r < 4; r++) { F2U a; a.f = cp[r]; ck[hh][r] = a.u; }
    }
    const float4 sb4 = *(const float4*)(g_SB + j*H_ + hb);

    u64 pvj[H_][2];
    #pragma unroll
    for (int h = 0; h < H_; h++) {
        const float4 v = *(const float4*)(g_PV + ((u64)j*H_ + h)*D_ + ch);
        pvj[h][0] = pack2f(v.x, v.y); pvj[h][1] = pack2f(v.z, v.w);
    }
    u64 bo[2];
    { const float4 v = *(const float4*)(bOe + ch);
      bo[0] = pack2f(v.x, v.y); bo[1] = pack2f(v.z, v.w); }

    int buf = 0;
    for (int i = ig; i < N_; i += 4) {
        const float4* ep = (const float4*)(e + ((u64)i*N_ + j)*D_);
        const float4 ea = ep[2*l], eb = ep[2*l + 1];
        u64 ev[4];
        ev[0] = pack2f(ea.x, ea.y); ev[1] = pack2f(ea.z, ea.w);
        ev[2] = pack2f(eb.x, eb.y); ev[3] = pack2f(eb.z, eb.w);

        // pv_i loads in flight during the reduce
        u64 pvi[H_][2];
        #pragma unroll
        for (int h = 0; h < H_; h++) {
            const float4 v = *(const float4*)(g_PV + ((u64)i*H_ + h)*D_ + ch);
            pvi[h][0] = pack2f(v.x, v.y); pvi[h][1] = pack2f(v.z, v.w);
        }

        float ds[4];
        #pragma unroll
        for (int hh = 0; hh < 4; hh++) {
            u64 as = 0ull;
            #pragma unroll
            for (int r = 0; r < 4; r++) dfma2(as, ev[r], ck[hh][r]);
            ds[hh] = hsum2(as);
        }
        #pragma unroll
        for (int hh = 0; hh < 4; hh++) ds[hh] = wredux(ds[hh]);

        if (l < 4) {
            const float sj = (l == 0) ? ds[0] + sb4.x :
                             (l == 1) ? ds[1] + sb4.y :
                             (l == 2) ? ds[2] + sb4.z : ds[3] + sb4.w;
            const float si = g_SI[((u64)i*N_ + j)*H_ + hb + l];
            const float ei = exp2f(si * L2E_);
            const float ej = exp2f(sj * L2E_);
            const float rc = __fdividef(1.f, ei + ej);
            ai_s[buf][ig][hb + l] = ei * rc;
            aj_s[buf][ig][hb + l] = ej * rc;
        }
        asm volatile("bar.sync %0, 64;" :: "r"(1 + ig) : "memory");

        const float4 ai0 = *(const float4*)&ai_s[buf][ig][0];
        const float4 ai1 = *(const float4*)&ai_s[buf][ig][4];
        const float4 aj0 = *(const float4*)&aj_s[buf][ig][0];
        const float4 aj1 = *(const float4*)&aj_s[buf][ig][4];
        const float ai8[8] = {ai0.x, ai0.y, ai0.z, ai0.w, ai1.x, ai1.y, ai1.z, ai1.w};
        const float aj8[8] = {aj0.x, aj0.y, aj0.z, aj0.w, aj1.x, aj1.y, aj1.z, aj1.w};

        u64 acc0 = bo[0], acc1 = bo[1];
        #pragma unroll
        for (int h = 0; h < H_; h++) {
            const u64 a = bcast2(ai8[h]);
            dfma2(acc0, a, pvi[h][0]); dfma2(acc1, a, pvi[h][1]);
            const u64 b = bcast2(aj8[h]);
            dfma2(acc0, b, pvj[h][0]); dfma2(acc1, b, pvj[h][1]);
        }
        F2U o0, o1; o0.u = acc0; o1.u = acc1;
        *(float4*)(eout + ((u64)i*N_ + j)*D_ + ch) =
            make_float4(o0.f.x, o0.f.y, o1.f.x, o1.f.y);
        buf ^= 1;
    }
}

// ---------------- F: x_out ---------------------------------------------------
__global__ void kF(const float* __restrict__ Wv_e, const float* __restrict__ bv_e,
                   const float* __restrict__ WOx, const float* __restrict__ bOx,
                   float* __restrict__ xout)
{
    __shared__ float we_s[H_*D_];
    __shared__ float xh_s[D_];
    const int t  = threadIdx.x;
    const int n0 = blockIdx.x * 8;
    const int h  = t >> 5, k = t & 31;

    for (int n = 0; n < 8; n++) {
        const int nn = n0 + n;
        __syncthreads();
        #pragma unroll
        for (int r = 0; r < H_; r++) we_s[r*D_ + t] = g_WE[nn*H_*D_ + r*D_ + t];
        __syncthreads();
        float acc = bv_e[h*DH_ + k];
        for (int d = 0; d < D_; d++)
            acc += we_s[h*D_ + d] * Wv_e[(h*D_ + d)*DH_ + k];
        xh_s[h*DH_ + k] = acc;
        __syncthreads();
        float o = bOx[t];
        for (int u = 0; u < D_; u++)
            o += xh_s[u] * WOx[u*D_ + t];
        xout[nn*D_ + t] = o;
    }
}

// ---------------- launcher ---------------------------------------------------
extern "C" void kernel_launch(void* const* d_in, const int* in_sizes, int n_in,
                              void* d_out, int out_size)
{
    const float* x    = (const float*)d_in[0];
    const float* e    = (const float*)d_in[1];
    const float* Wq_x = (const float*)d_in[2];
    const float* bq_x = (const float*)d_in[3];
    const float* Wk_e = (const float*)d_in[4];
    const float* bk_e = (const float*)d_in[5];
    const float* Wv_e = (const float*)d_in[6];
    const float* bv_e = (const float*)d_in[7];
    const float* Wq_e = (const float*)d_in[8];
    const float* bq_e = (const float*)d_in[9];
    const float* Wk_x = (const float*)d_in[10];
    const float* bk_x = (const float*)d_in[11];
    const float* Wv_x = (const float*)d_in[12];
    const float* bv_x = (const float*)d_in[13];
    const float* WOx  = (const float*)d_in[14];
    const float* bOx  = (const float*)d_in[15];
    const float* WOe  = (const float*)d_in[16];
    const float* bOe  = (const float*)d_in[17];

    float* xout = (float*)d_out;                 // [384,256]
    float* eout = (float*)d_out + N_*D_;         // [384,384,256]

    kP <<<48,  256>>>(x, Wq_x, bq_x, Wk_x, bk_x, Wv_x, bv_x,
                      Wk_e, bk_e, Wq_e, bq_e, WOe);
    kM1<<<N_, 256>>>(e);
    kM2<<<N_, 256>>>(e, bOe, eout);
    kF <<<48,  256>>>(Wv_e, bv_e, WOx, bOx, xout);
}

// round 12
// speedup vs baseline: 1.6565x; 1.6565x over previous
#include <cuda_runtime.h>
#include <cuda_bf16.h>

#define N_ 384
#define D_ 256
#define H_ 8
#define DH_ 32
#define SCALE_ 0.17677669529663687f
#define L2E_ 1.4426950408889634f

typedef unsigned long long u64;

// ---------------- scratch (device globals; no allocation allowed) ----------
__device__ __align__(16) float g_Q [N_*H_*DH_];
__device__ __align__(16) float g_K [N_*H_*DH_];
__device__ __align__(16) float g_V [N_*H_*DH_];
__device__ __align__(16) float g_KQ[N_*H_*D_];   // [n][h][d] scale folded
__device__ __align__(16) float g_CK[N_*H_*D_];   // [n][h][d] scale folded
__device__ __align__(16) float g_PV[N_*H_*D_];   // [n][h][c]
__device__ __align__(16) float g_CB[N_*H_];
__device__ __align__(16) float g_SB[N_*H_];
__device__ __align__(16) float g_LS[N_*H_];
__device__ __align__(16) float g_SI[(size_t)N_*N_*H_];   // [i][j][h]
__device__ __align__(16) float g_P [(size_t)N_*N_*H_];   // [i][j][h] unnormalized
__device__ __align__(16) float g_AI[(size_t)N_*N_*H_];   // [j][i][h]  (transposed!)
__device__ __align__(16) float g_AJ[(size_t)N_*N_*H_];   // [j][i][h]

// ---------------- packed f32x2 helpers -------------------------------------
union F2U { float2 f; u64 u; };

__device__ __forceinline__ void dfma2(u64 &d, u64 a, u64 b) {
    asm("fma.rn.f32x2 %0, %1, %2, %0;" : "+l"(d) : "l"(a), "l"(b));
}
__device__ __forceinline__ u64 bcast2(float v) {
    F2U t; t.f.x = v; t.f.y = v; return t.u;
}
__device__ __forceinline__ float hsum2(u64 a) {
    F2U t; t.u = a; return t.f.x + t.f.y;
}
__device__ __forceinline__ u64 pack2f(float a, float b) {
    F2U t; t.f.x = a; t.f.y = b; return t.u;
}

// ---------------- P1: qx/kx/vx + cb/sb -------------------------------------
__global__ void kP1(const float* __restrict__ x,
                    const float* __restrict__ Wq_x, const float* __restrict__ bq_x,
                    const float* __restrict__ Wk_x, const float* __restrict__ bk_x,
                    const float* __restrict__ Wv_x, const float* __restrict__ bv_x,
                    const float* __restrict__ bk_e, const float* __restrict__ bq_e)
{
    __shared__ float x_s[8][D_];
    __shared__ float q_s[8][H_][DH_];
    __shared__ float k_s[8][H_][DH_];
    __shared__ float v_s[8][H_][DH_];
    const int t  = threadIdx.x;
    const int n0 = blockIdx.x * 8;

    #pragma unroll
    for (int n = 0; n < 8; n++) x_s[n][t] = x[(n0 + n) * D_ + t];
    __syncthreads();

    {
        const int h = t >> 5, k = t & 31;
        float aq[8], ak[8], av[8];
        const float bq = bq_x[h*DH_ + k], bk = bk_x[h*DH_ + k], bv = bv_x[h*DH_ + k];
        #pragma unroll
        for (int n = 0; n < 8; n++) { aq[n] = bq; ak[n] = bk; av[n] = bv; }
        for (int d = 0; d < D_; d++) {
            const float wq = Wq_x[(h*D_ + d)*DH_ + k];
            const float wk = Wk_x[(h*D_ + d)*DH_ + k];
            const float wv = Wv_x[(h*D_ + d)*DH_ + k];
            #pragma unroll
            for (int n = 0; n < 8; n++) {
                const float xv = x_s[n][d];
                aq[n] += xv * wq; ak[n] += xv * wk; av[n] += xv * wv;
            }
        }
        #pragma unroll
        for (int n = 0; n < 8; n++) {
            q_s[n][h][k] = aq[n]; k_s[n][h][k] = ak[n]; v_s[n][h][k] = av[n];
        }
    }
    __syncthreads();

    if (t < 64) {
        const int n = t >> 3, hh = t & 7;
        float cb = 0.f, sb = 0.f;
        #pragma unroll
        for (int kk = 0; kk < DH_; kk++) {
            cb += q_s[n][hh][kk] * bk_e[hh*DH_ + kk];
            sb += k_s[n][hh][kk] * bq_e[hh*DH_ + kk];
        }
        g_CB[(n0 + n)*H_ + hh] = cb * SCALE_;
        g_SB[(n0 + n)*H_ + hh] = sb * SCALE_;
    }

    // linear dump: q_s[n][h][k] (idx = n*256+h*32+k) -> g_Q[n0*256 + idx]
    const float* qs = (const float*)q_s;
    const float* ks = (const float*)k_s;
    const float* vs = (const float*)v_s;
    for (int idx = t; idx < 2048; idx += 256) {
        g_Q[n0*256 + idx] = qs[idx];
        g_K[n0*256 + idx] = ks[idx];
        g_V[n0*256 + idx] = vs[idx];
    }
}

// ---------------- P2: kq, ck, pv -------------------------------------------
// Grid (48 node-groups, 8 heads), 256 thr (= d channel).
__global__ void kP2(const float* __restrict__ Wk_e,
                    const float* __restrict__ Wq_e,
                    const float* __restrict__ WOe)
{
    __shared__ float q8[8][DH_], k8[8][DH_], v8[8][DH_];
    const int n0 = blockIdx.x * 8;
    const int hh = blockIdx.y;
    const int t  = threadIdx.x;

    {   // t = n*32+k covers 8 nodes x 32 k
        const int n = t >> 5, k = t & 31;
        q8[n][k] = g_Q[((n0 + n)*H_ + hh)*DH_ + k];
        k8[n][k] = g_K[((n0 + n)*H_ + hh)*DH_ + k];
        v8[n][k] = g_V[((n0 + n)*H_ + hh)*DH_ + k];
    }
    __syncthreads();

    float akq[8], ack[8], apv[8];
    #pragma unroll
    for (int n = 0; n < 8; n++) { akq[n] = 0.f; ack[n] = 0.f; apv[n] = 0.f; }

    #pragma unroll 4
    for (int k = 0; k < DH_; k++) {
        const float wk = Wk_e[(hh*D_ + t)*DH_ + k];
        const float wq = Wq_e[(hh*D_ + t)*DH_ + k];
        const float wo = WOe[(hh*DH_ + k)*D_ + t];
        #pragma unroll
        for (int n = 0; n < 8; n++) {
            akq[n] += wk * q8[n][k];
            ack[n] += wq * k8[n][k];
            apv[n] += wo * v8[n][k];
        }
    }
    #pragma unroll
    for (int n = 0; n < 8; n++) {
        const int base = ((n0 + n)*H_ + hh)*D_ + t;
        g_KQ[base] = akq[n] * SCALE_;
        g_CK[base] = ack[n] * SCALE_;
        g_PV[base] = apv[n];
    }
}

// ---------------- S: row dots -- s_i store, p store, lsum -------------------
// Block = row i, 384 threads, thread = j. No cross-lane reduce in hot loop.
__global__ void __launch_bounds__(384) kS(const float* __restrict__ e)
{
    __shared__ u64 kq2[H_][D_/2];    // broadcast operands
    __shared__ u64 ck2[H_][D_/2];
    __shared__ float cbs[H_], sbs[H_], ls_s[H_];
    const int i = blockIdx.x;
    const int t = threadIdx.x;

    {
        const u64* kqsrc = (const u64*)(g_KQ + i*H_*D_);
        const u64* cksrc = (const u64*)(g_CK + i*H_*D_);
        u64* kqd = (u64*)kq2;  u64* ckd = (u64*)ck2;
        for (int idx = t; idx < H_*D_/2; idx += 384) { kqd[idx] = kqsrc[idx]; ckd[idx] = cksrc[idx]; }
    }
    if (t < H_) { cbs[t] = g_CB[i*H_ + t]; sbs[t] = g_SB[i*H_ + t]; ls_s[t] = 0.f; }
    __syncthreads();

    u64 aq[H_], as[H_];
    #pragma unroll
    for (int h = 0; h < H_; h++) { aq[h] = 0ull; as[h] = 0ull; }

    const float4* ep = (const float4*)(e + ((size_t)i*N_ + t)*D_);
    #pragma unroll 2
    for (int c = 0; c < 64; c++) {
        const float4 ev = ep[c];
        const u64 e0 = pack2f(ev.x, ev.y), e1 = pack2f(ev.z, ev.w);
        #pragma unroll
        for (int h = 0; h < H_; h++) {
            dfma2(aq[h], e0, kq2[h][2*c]); dfma2(aq[h], e1, kq2[h][2*c + 1]);
            dfma2(as[h], e0, ck2[h][2*c]); dfma2(as[h], e1, ck2[h][2*c + 1]);
        }
    }

    float si[H_], pv[H_];
    #pragma unroll
    for (int h = 0; h < H_; h++) {
        si[h] = hsum2(as[h]) + sbs[h];
        // scores O(+-5): exp2 cannot overflow; softmax shift-invariant.
        pv[h] = exp2f((hsum2(aq[h]) + cbs[h]) * L2E_);
    }
    float4* sip = (float4*)(g_SI + ((size_t)i*N_ + t)*H_);
    sip[0] = make_float4(si[0], si[1], si[2], si[3]);
    sip[1] = make_float4(si[4], si[5], si[6], si[7]);
    float4* pp = (float4*)(g_P + ((size_t)i*N_ + t)*H_);
    pp[0] = make_float4(pv[0], pv[1], pv[2], pv[3]);
    pp[1] = make_float4(pv[4], pv[5], pv[6], pv[7]);

    // lsum: butterfly once, then smem atomic
    #pragma unroll
    for (int h = 0; h < H_; h++) {
        float v = pv[h];
        #pragma unroll
        for (int o = 16; o; o >>= 1) v += __shfl_xor_sync(0xffffffffu, v, o);
        pv[h] = v;
    }
    const int l = t & 31;
    if (l < H_) atomicAdd(&ls_s[l], pv[l]);
    __syncthreads();
    if (t < H_) g_LS[i*H_ + t] = ls_s[t];
}

// ---------------- T: column dots -- s_j, 2-way softmax -> ai/aj -------------
// Block = col j, 384 threads, thread = i. Writes transposed [j][i][h].
__global__ void __launch_bounds__(384) kT(const float* __restrict__ e)
{
    __shared__ u64 ck2[H_][D_/2];
    __shared__ float sbs[H_];
    const int j = blockIdx.x;
    const int t = threadIdx.x;            // = i

    {
        const u64* cksrc = (const u64*)(g_CK + j*H_*D_);
        u64* ckd = (u64*)ck2;
        for (int idx = t; idx < H_*D_/2; idx += 384) ckd[idx] = cksrc[idx];
    }
    if (t < H_) sbs[t] = g_SB[j*H_ + t];
    __syncthreads();

    u64 as[H_];
    #pragma unroll
    for (int h = 0; h < H_; h++) as[h] = 0ull;

    const float4* ep = (const float4*)(e + ((size_t)t*N_ + j)*D_);
    #pragma unroll 2
    for (int c = 0; c < 64; c++) {
        const float4 ev = ep[c];
        const u64 e0 = pack2f(ev.x, ev.y), e1 = pack2f(ev.z, ev.w);
        #pragma unroll
        for (int h = 0; h < H_; h++) {
            dfma2(as[h], e0, ck2[h][2*c]); dfma2(as[h], e1, ck2[h][2*c + 1]);
        }
    }

    const float4 siA = *(const float4*)(g_SI + ((size_t)t*N_ + j)*H_);
    const float4 siB = *(const float4*)(g_SI + ((size_t)t*N_ + j)*H_ + 4);
    const float si[8] = {siA.x, siA.y, siA.z, siA.w, siB.x, siB.y, siB.z, siB.w};

    float ai[H_], aj[H_];
    #pragma unroll
    for (int h = 0; h < H_; h++) {
        const float sj = hsum2(as[h]) + sbs[h];
        const float ei = exp2f(si[h] * L2E_);
        const float ej = exp2f(sj    * L2E_);
        const float rc = __fdividef(1.f, ei + ej);
        ai[h] = ei * rc; aj[h] = ej * rc;
    }
    float4* aip = (float4*)(g_AI + ((size_t)j*N_ + t)*H_);
    aip[0] = make_float4(ai[0], ai[1], ai[2], ai[3]);
    aip[1] = make_float4(ai[4], ai[5], ai[6], ai[7]);
    float4* ajp = (float4*)(g_AJ + ((size_t)j*N_ + t)*H_);
    ajp[0] = make_float4(aj[0], aj[1], aj[2], aj[3]);
    ajp[1] = make_float4(aj[4], aj[5], aj[6], aj[7]);
}

// ---------------- E: eout = sum_h ai*pv_i + aj*pv_j + bOe -------------------
// Grid (48 i-tiles of 8, 4 j-slices), 256 thr: tt = ch-pair, ih = i-half.
__global__ void __launch_bounds__(256) kE(const float* __restrict__ bOe,
                                          float* __restrict__ eout)
{
    const int i0 = blockIdx.x * 8;
    const int t  = threadIdx.x;
    const int tt = t & 127, ih = t >> 7;
    const int cp = 2 * tt;                      // channel pair base

    u64 pvi[4][H_];
    #pragma unroll
    for (int q = 0; q < 4; q++)
        #pragma unroll
        for (int h = 0; h < H_; h++)
            pvi[q][h] = *(const u64*)(g_PV + ((size_t)(i0 + ih*4 + q)*H_ + h)*D_ + cp);
    const u64 bo = *(const u64*)(bOe + cp);

    const int j0 = blockIdx.y * 96;
    for (int j = j0; j < j0 + 96; j++) {
        u64 pvj[H_];
        #pragma unroll
        for (int h = 0; h < H_; h++)
            pvj[h] = *(const u64*)(g_PV + ((size_t)j*H_ + h)*D_ + cp);
        #pragma unroll
        for (int q = 0; q < 4; q++) {
            const int irow = i0 + ih*4 + q;
            const float4 aiA = *(const float4*)(g_AI + ((size_t)j*N_ + irow)*H_);
            const float4 aiB = *(const float4*)(g_AI + ((size_t)j*N_ + irow)*H_ + 4);
            const float4 ajA = *(const float4*)(g_AJ + ((size_t)j*N_ + irow)*H_);
            const float4 ajB = *(const float4*)(g_AJ + ((size_t)j*N_ + irow)*H_ + 4);
            const float ai8[8] = {aiA.x, aiA.y, aiA.z, aiA.w, aiB.x, aiB.y, aiB.z, aiB.w};
            const float aj8[8] = {ajA.x, ajA.y, ajA.z, ajA.w, ajB.x, ajB.y, ajB.z, ajB.w};
            u64 acc = bo;
            #pragma unroll
            for (int h = 0; h < H_; h++) {
                dfma2(acc, bcast2(ai8[h]), pvi[q][h]);
                dfma2(acc, bcast2(aj8[h]), pvj[h]);
            }
            *(u64*)(eout + ((size_t)irow*N_ + j)*D_ + cp) = acc;
        }
    }
}

// ---------------- WF: we recompute + x projections (one node per block) -----
__global__ void __launch_bounds__(256) kWF(const float* __restrict__ e,
                                           const float* __restrict__ Wv_e,
                                           const float* __restrict__ bv_e,
                                           const float* __restrict__ WOx,
                                           const float* __restrict__ bOx,
                                           float* __restrict__ xout)
{
    __shared__ float p_s[N_*H_];     // 12 KB
    __shared__ float ls_s[H_];
    __shared__ float we_s[H_][D_];
    __shared__ float xh_s[D_];
    const int i = blockIdx.x;
    const int t = threadIdx.x;

    {
        const float4* src = (const float4*)(g_P + (size_t)i*N_*H_);
        float4* dst = (float4*)p_s;
        for (int idx = t; idx < N_*H_/4; idx += 256) dst[idx] = src[idx];
    }
    if (t < H_) ls_s[t] = g_LS[i*H_ + t];
    __syncthreads();

    float we[H_];
    #pragma unroll
    for (int h = 0; h < H_; h++) we[h] = 0.f;

    const float* erow = e + (size_t)i*N_*D_ + t;
    #pragma unroll 4
    for (int j = 0; j < N_; j++) {
        const float ev = erow[(size_t)j*D_];
        const float4 pA = *(const float4*)&p_s[j*H_];
        const float4 pB = *(const float4*)&p_s[j*H_ + 4];
        we[0] += pA.x*ev; we[1] += pA.y*ev; we[2] += pA.z*ev; we[3] += pA.w*ev;
        we[4] += pB.x*ev; we[5] += pB.y*ev; we[6] += pB.z*ev; we[7] += pB.w*ev;
    }
    #pragma unroll
    for (int h = 0; h < H_; h++)
        we_s[h][t] = we[h] * __fdividef(1.f, ls_s[h]);
    __syncthreads();

    // x_heads[h][k] = bv + sum_d we[h][d] * Wv_e[h][d][k]
    const int h = t >> 5, k = t & 31;
    float acc = bv_e[h*DH_ + k];
    #pragma unroll 4
    for (int d = 0; d < D_; d++)
        acc += we_s[h][d] * Wv_e[(h*D_ + d)*DH_ + k];
    xh_s[t] = acc;                   // t = h*32+k
    __syncthreads();

    float o = bOx[t];
    #pragma unroll 4
    for (int u = 0; u < D_; u++)
        o += xh_s[u] * WOx[u*D_ + t];
    xout[i*D_ + t] = o;
}

// ---------------- launcher ---------------------------------------------------
extern "C" void kernel_launch(void* const* d_in, const int* in_sizes, int n_in,
                              void* d_out, int out_size)
{
    const float* x    = (const float*)d_in[0];
    const float* e    = (const float*)d_in[1];
    const float* Wq_x = (const float*)d_in[2];
    const float* bq_x = (const float*)d_in[3];
    const float* Wk_e = (const float*)d_in[4];
    const float* bk_e = (const float*)d_in[5];
    const float* Wv_e = (const float*)d_in[6];
    const float* bv_e = (const float*)d_in[7];
    const float* Wq_e = (const float*)d_in[8];
    const float* bq_e = (const float*)d_in[9];
    const float* Wk_x = (const float*)d_in[10];
    const float* bk_x = (const float*)d_in[11];
    const float* Wv_x = (const float*)d_in[12];
    const float* bv_x = (const float*)d_in[13];
    const float* WOx  = (const float*)d_in[14];
    const float* bOx  = (const float*)d_in[15];
    const float* WOe  = (const float*)d_in[16];
    const float* bOe  = (const float*)d_in[17];

    float* xout = (float*)d_out;                 // [384,256]
    float* eout = (float*)d_out + N_*D_;         // [384,384,256]

    kP1<<<48, 256>>>(x, Wq_x, bq_x, Wk_x, bk_x, Wv_x, bv_x, bk_e, bq_e);
    kP2<<<dim3(48, 8), 256>>>(Wk_e, Wq_e, WOe);
    kS <<<N_, 384>>>(e);
    kT <<<N_, 384>>>(e);
    kE <<<dim3(48, 4), 256>>>(bOe, eout);
    kWF<<<N_, 256>>>(e, Wv_e, bv_e, WOx, bOx, xout);
}